// round 7
// baseline (speedup 1.0000x reference)
#include <cuda_runtime.h>
#include <float.h>

#define NATOMS 10000
#define NPAIRS 160000
#define HPITCH 192   // padded h row: [q0(128) | filtered(50) | d(1) | zero pad(13)]

// ---------------- scratch (device globals; no allocation allowed) ----------------
__device__ float g_h[(size_t)NPAIRS * HPITCH];     // edge feature rows
__device__ float g_hidden[(size_t)NPAIRS * 64];
__device__ float g_m[(size_t)NPAIRS * 64];         // q_ij_mtx
__device__ float g_att[(size_t)NPAIRS * 4];
__device__ float g_e[(size_t)NPAIRS * 4];
__device__ float g_segmax[NATOMS * 4];
__device__ float g_denom[NATOMS * 4];
__device__ int   g_counts[NATOMS];
__device__ int   g_cursor[NATOMS];
__device__ int   g_offs[NATOMS + 1];
__device__ int   g_order[NPAIRS];
__device__ float g_coeffs[(size_t)NPAIRS * 256];
__device__ float g_norm[(size_t)NATOMS * 256];
__device__ float g_h2[(size_t)NATOMS * 384];       // [q(64) | q_ij(256) | q_comb(64)]
__device__ float g_t1[(size_t)NATOMS * 64];
__device__ float g_t2[(size_t)NATOMS * 64];

// ---------------- helpers ----------------
__device__ __forceinline__ float siluf(float x) { return x / (1.f + __expf(-x)); }
__device__ __forceinline__ float fast_tanh(float x) {
    return 1.f - 2.f / (__expf(2.f * x) + 1.f);
}
__device__ __forceinline__ void atomicMaxFloat(float* a, float v) {
    if (v >= 0.f) atomicMax((int*)a, __float_as_int(v));
    else          atomicMin((unsigned int*)a, __float_as_uint(v));
}

// ---------------- init ----------------
__global__ void k_init() {
    int i = blockIdx.x * blockDim.x + threadIdx.x;
    if (i < NATOMS * 4) { g_segmax[i] = -FLT_MAX; g_denom[i] = 0.f; }
    if (i < NATOMS)     { g_counts[i] = 0; g_cursor[i] = 0; }
}

// ---------------- gather: build q0 | d | zero-pad rows of g_h ----------------
__global__ void k_gather(const float* __restrict__ q, const int* __restrict__ idx_i,
                         const int* __restrict__ idx_j, const float* __restrict__ d_ij) {
    int p    = blockIdx.x * 8 + (threadIdx.x >> 5);
    int lane = threadIdx.x & 31;
    int i = idx_i[p], j = idx_j[p];
    float* hr = g_h + (size_t)p * HPITCH;
    const float* qi = q + (size_t)i * 64;
    const float* qj = q + (size_t)j * 64;
    hr[lane]      = qi[lane];       hr[32 + lane] = qi[32 + lane];
    hr[64 + lane] = qj[lane];       hr[96 + lane] = qj[32 + lane];
    if (lane < 14) hr[178 + lane] = (lane == 0) ? d_ij[p] : 0.f;
}

// ---------------- generic tiled GEMM: C = epi(A @ W^T + b) ----------------
// BM=64, BN=64, BK=16, 256 threads, 4x4 register tile per thread.
// MODE 0: h[:, :128] @ w_in^T,  epi: rbf * (.)  -> writes g_h cols 128..177
// MODE 1: h @ w_out1^T, silu -> g_hidden
// MODE 2: hidden @ w_out2^T, +bias -> g_m
// MODE 3: (m x comb outer) @ w_mix^T, tanh -> g_coeffs   (A built on the fly)
// MODE 4: norm @ w_post1^T, silu -> g_t1
// MODE 5: t1 @ w_post2^T, silu -> g_h2[:, 320:384]
// MODE 6: h2 @ w_node1^T, silu -> g_t2
// MODE 7: t2 @ w_node2^T, q + silu(.) -> out
template <int MODE>
__global__ void k_gemm(const float* __restrict__ W, const float* __restrict__ bias,
                       const float* __restrict__ x1, const float* __restrict__ x2,
                       const float* __restrict__ x3, const int* __restrict__ xi,
                       float* __restrict__ outp) {
    constexpr int M  = (MODE <= 3) ? NPAIRS : NATOMS;
    constexpr int KT = (MODE == 0) ? 8  : (MODE == 1) ? 12 : (MODE == 2) ? 4 :
                       (MODE == 3) ? 16 : (MODE == 4) ? 16 : (MODE == 5) ? 4 :
                       (MODE == 6) ? 24 : 4;
    constexpr int KW = (MODE == 0) ? 128 : (MODE == 1) ? 179 : (MODE == 2) ? 64 :
                       (MODE == 3) ? 256 : (MODE == 4) ? 256 : (MODE == 5) ? 64 :
                       (MODE == 6) ? 384 : 64;
    constexpr int NW  = (MODE == 3) ? 256 : (MODE == 0) ? 50 : 64;
    constexpr int LDA = (MODE <= 1) ? HPITCH : (MODE == 4) ? 256 : (MODE == 6) ? 384 : 64;
    constexpr int LDC = (MODE == 0) ? HPITCH : (MODE == 3) ? 256 : (MODE == 5) ? 384 : 64;

    const float* A = nullptr;
    float* C = nullptr;
    if constexpr (MODE == 0)      { A = g_h;      C = g_h + 128; }
    else if constexpr (MODE == 1) { A = g_h;      C = g_hidden;  }
    else if constexpr (MODE == 2) { A = g_hidden; C = g_m;       }
    else if constexpr (MODE == 3) {               C = g_coeffs;  }
    else if constexpr (MODE == 4) { A = g_norm;   C = g_t1;      }
    else if constexpr (MODE == 5) { A = g_t1;     C = g_h2 + 320;}
    else if constexpr (MODE == 6) { A = g_h2;     C = g_t2;      }
    else                          { A = g_t2;     C = outp;      }

    __shared__ __align__(16) float sA[16 * 68];
    __shared__ __align__(16) float sW[16 * 68];

    int t  = threadIdx.x;
    int p0 = blockIdx.x * 64;
    int nb = (MODE == 3) ? blockIdx.y : 0;
    int tx = t & 15, ty = t >> 4;

    int am   = t >> 2;          // staging row within tile (A rows / W rows)
    int ak   = (t & 3) * 4;     // staging k offset (float4)
    int arow = p0 + am;

    float4 comb = make_float4(0.f, 0.f, 0.f, 0.f);
    const float* mrow = nullptr;
    if constexpr (MODE == 3) {
        if (arow < M) {
            int jj = xi[arow];
            comb.x = g_e[arow * 4 + 0] / g_denom[jj * 4 + 0];
            comb.y = g_e[arow * 4 + 1] / g_denom[jj * 4 + 1];
            comb.z = g_e[arow * 4 + 2] / g_denom[jj * 4 + 2];
            comb.w = g_e[arow * 4 + 3] / g_denom[jj * 4 + 3];
            mrow = g_m + (size_t)arow * 64;
        }
    }

    float acc[4][4];
#pragma unroll
    for (int i = 0; i < 4; i++)
#pragma unroll
        for (int j = 0; j < 4; j++) acc[i][j] = 0.f;

    for (int kt = 0; kt < KT; kt++) {
        int k0 = kt * 16;
        // fetch A fragment
        float4 av = make_float4(0.f, 0.f, 0.f, 0.f);
        if constexpr (MODE == 3) {
            if (arow < M) {
                float mv = __ldg(&mrow[(k0 >> 2) + (t & 3)]);  // k = k0+ak+j -> f = k>>2
                av.x = mv * comb.x; av.y = mv * comb.y;
                av.z = mv * comb.z; av.w = mv * comb.w;
            }
        } else {
            if (arow < M)
                av = *reinterpret_cast<const float4*>(A + (size_t)arow * LDA + k0 + ak);
        }
        // fetch W fragment (scalar, zero-padded)
        int gnW = nb * 64 + am;
        float wv[4];
#pragma unroll
        for (int j = 0; j < 4; j++) {
            int k = k0 + ak + j;
            wv[j] = (gnW < NW && k < KW) ? __ldg(&W[(size_t)gnW * KW + k]) : 0.f;
        }
        __syncthreads();
        sA[(ak + 0) * 68 + am] = av.x; sA[(ak + 1) * 68 + am] = av.y;
        sA[(ak + 2) * 68 + am] = av.z; sA[(ak + 3) * 68 + am] = av.w;
#pragma unroll
        for (int j = 0; j < 4; j++) sW[(ak + j) * 68 + am] = wv[j];
        __syncthreads();
#pragma unroll
        for (int kk = 0; kk < 16; kk++) {
            float4 a = *reinterpret_cast<const float4*>(&sA[kk * 68 + ty * 4]);
            float4 b = *reinterpret_cast<const float4*>(&sW[kk * 68 + tx * 4]);
            acc[0][0] += a.x * b.x; acc[0][1] += a.x * b.y; acc[0][2] += a.x * b.z; acc[0][3] += a.x * b.w;
            acc[1][0] += a.y * b.x; acc[1][1] += a.y * b.y; acc[1][2] += a.y * b.z; acc[1][3] += a.y * b.w;
            acc[2][0] += a.z * b.x; acc[2][1] += a.z * b.y; acc[2][2] += a.z * b.z; acc[2][3] += a.z * b.w;
            acc[3][0] += a.w * b.x; acc[3][1] += a.w * b.y; acc[3][2] += a.w * b.z; acc[3][3] += a.w * b.w;
        }
    }

#pragma unroll
    for (int i = 0; i < 4; i++) {
        int p = p0 + ty * 4 + i;
        if (p >= M) continue;
        float dv = 0.f;
        if constexpr (MODE == 0) dv = x1[p];
#pragma unroll
        for (int j = 0; j < 4; j++) {
            int gn = nb * 64 + tx * 4 + j;
            float v = acc[i][j];
            if constexpr (MODE == 0) {
                if (gn < 50) {
                    float off = x2[gn], wd = x3[gn];
                    float dd = dv - off;
                    float r = __expf((-0.5f / (wd * wd)) * dd * dd);
                    C[(size_t)p * LDC + gn] = r * (v + bias[gn]);
                }
            } else if constexpr (MODE == 2) {
                C[(size_t)p * LDC + gn] = v + bias[gn];
            } else if constexpr (MODE == 3) {
                C[(size_t)p * LDC + gn] = fast_tanh(v);
            } else if constexpr (MODE == 7) {
                C[(size_t)p * LDC + gn] = x1[(size_t)p * 64 + gn] + siluf(v + bias[gn]);
            } else {
                C[(size_t)p * LDC + gn] = siluf(v + bias[gn]);
            }
        }
    }
}

// ---------------- attention logits + segment max + degree counts ----------------
__global__ void k_att(const float* __restrict__ w_att, const float* __restrict__ b_att,
                      const int* __restrict__ idx_j) {
    int p    = blockIdx.x * 8 + (threadIdx.x >> 5);
    int lane = threadIdx.x & 31;
    const float* mr = g_m + (size_t)p * 64;
    float m1 = mr[lane], m2 = mr[32 + lane];
    float pa[4];
#pragma unroll
    for (int a = 0; a < 4; a++)
        pa[a] = __ldg(&w_att[a * 64 + lane]) * m1 + __ldg(&w_att[a * 64 + 32 + lane]) * m2;
#pragma unroll
    for (int o = 16; o > 0; o >>= 1)
#pragma unroll
        for (int a = 0; a < 4; a++) pa[a] += __shfl_xor_sync(0xffffffffu, pa[a], o);
    if (lane == 0) {
        int j = idx_j[p];
#pragma unroll
        for (int a = 0; a < 4; a++) {
            float v = pa[a] + b_att[a];
            v = (v >= 0.f) ? v : 2.f * expm1f(0.5f * v);   // celu alpha=2
            g_att[p * 4 + a] = v;
            atomicMaxFloat(&g_segmax[j * 4 + a], v);
        }
        atomicAdd(&g_counts[j], 1);
    }
}

// ---------------- softmax numerators + denominators ----------------
__global__ void k_exp(const int* __restrict__ idx_j) {
    int p = blockIdx.x * blockDim.x + threadIdx.x;
    if (p >= NPAIRS) return;
    int j = idx_j[p];
#pragma unroll
    for (int a = 0; a < 4; a++) {
        float v = __expf(g_att[p * 4 + a] - g_segmax[j * 4 + a]);
        g_e[p * 4 + a] = v;
        atomicAdd(&g_denom[j * 4 + a], v);
    }
}

// ---------------- exclusive scan of counts -> offs (single block) ----------------
__global__ void k_scan() {
    __shared__ int part[1024];
    int tid = threadIdx.x;
    int base = tid * 10;
    int loc[10];
    int s = 0;
#pragma unroll
    for (int j = 0; j < 10; j++) {
        int idx = base + j;
        int v = (idx < NATOMS) ? g_counts[idx] : 0;
        loc[j] = s; s += v;
    }
    part[tid] = s;
    __syncthreads();
    for (int off = 1; off < 1024; off <<= 1) {
        int v = (tid >= off) ? part[tid - off] : 0;
        __syncthreads();
        part[tid] += v;
        __syncthreads();
    }
    int pre = (tid > 0) ? part[tid - 1] : 0;
#pragma unroll
    for (int j = 0; j < 10; j++) {
        int idx = base + j;
        if (idx < NATOMS) g_offs[idx] = pre + loc[j];
    }
    if (tid == 1023) g_offs[NATOMS] = part[1023];
}

// ---------------- fill CSR edge order ----------------
__global__ void k_fill(const int* __restrict__ idx_j) {
    int p = blockIdx.x * blockDim.x + threadIdx.x;
    if (p >= NPAIRS) return;
    int j = idx_j[p];
    int pos = atomicAdd(&g_cursor[j], 1);
    g_order[g_offs[j] + pos] = p;
}

// ---------------- per-atom gather reductions: q_ij, norm; also copy q into h2 ----
__global__ void k_segreduce(const float* __restrict__ q, const float* __restrict__ r_ij,
                            const float* __restrict__ d_ij) {
    int n    = blockIdx.x * 8 + (threadIdx.x >> 5);
    int lane = threadIdx.x & 31;
    if (n >= NATOMS) return;
    int beg = g_offs[n], end = g_offs[n + 1];
    int cnt = end - beg;
    float inv = 1.f / (float)max(cnt, 1);
    g_h2[(size_t)n * 384 + lane]      = q[(size_t)n * 64 + lane];
    g_h2[(size_t)n * 384 + 32 + lane] = q[(size_t)n * 64 + 32 + lane];
    for (int cr = 0; cr < 8; cr++) {
        int c = cr * 32 + lane;
        int f = c >> 2, hh = c & 3;
        float invd = 1.f / g_denom[n * 4 + hh];   // unused when cnt==0
        float ax = 0.f, ay = 0.f, az = 0.f, aq = 0.f;
        for (int tt = beg; tt < end; tt++) {
            int p = g_order[tt];
            float co   = __ldg(&g_coeffs[(size_t)p * 256 + c]);
            float rinv = 1.f / (__ldg(&d_ij[p]) + 1e-5f);
            ax += co * __ldg(&r_ij[p * 3 + 0]) * rinv;
            ay += co * __ldg(&r_ij[p * 3 + 1]) * rinv;
            az += co * __ldg(&r_ij[p * 3 + 2]) * rinv;
            aq += __ldg(&g_m[(size_t)p * 64 + f]) * __ldg(&g_e[p * 4 + hh]) * invd;
        }
        float mx = ax * inv, my = ay * inv, mz = az * inv;
        g_norm[(size_t)n * 256 + c]     = mx * mx + my * my + mz * mz;
        g_h2[(size_t)n * 384 + 64 + c]  = aq;
    }
}

// ---------------- launch ----------------
extern "C" void kernel_launch(void* const* d_in, const int* in_sizes, int n_in,
                              void* d_out, int out_size) {
    (void)in_sizes; (void)n_in; (void)out_size;
    const float* q       = (const float*)d_in[0];
    const float* r_ij    = (const float*)d_in[2];
    const float* d_ij    = (const float*)d_in[3];
    const int*   idx_i   = (const int*)d_in[4];
    const int*   idx_j   = (const int*)d_in[5];
    const float* rbf_off = (const float*)d_in[6];
    const float* rbf_w   = (const float*)d_in[7];
    const float* w_in    = (const float*)d_in[8];
    const float* b_in    = (const float*)d_in[9];
    const float* w_out1  = (const float*)d_in[10];
    const float* b_out1  = (const float*)d_in[11];
    const float* w_out2  = (const float*)d_in[12];
    const float* b_out2  = (const float*)d_in[13];
    const float* w_att   = (const float*)d_in[14];
    const float* b_att   = (const float*)d_in[15];
    const float* w_mix   = (const float*)d_in[16];
    const float* w_post1 = (const float*)d_in[17];
    const float* b_post1 = (const float*)d_in[18];
    const float* w_post2 = (const float*)d_in[19];
    const float* b_post2 = (const float*)d_in[20];
    const float* w_node1 = (const float*)d_in[21];
    const float* b_node1 = (const float*)d_in[22];
    const float* w_node2 = (const float*)d_in[23];
    const float* b_node2 = (const float*)d_in[24];
    float* out = (float*)d_out;

    k_init<<<157, 256>>>();
    k_gather<<<NPAIRS / 8, 256>>>(q, idx_i, idx_j, d_ij);
    k_gemm<0><<<NPAIRS / 64, 256>>>(w_in, b_in, d_ij, rbf_off, rbf_w, nullptr, nullptr);
    k_gemm<1><<<NPAIRS / 64, 256>>>(w_out1, b_out1, nullptr, nullptr, nullptr, nullptr, nullptr);
    k_gemm<2><<<NPAIRS / 64, 256>>>(w_out2, b_out2, nullptr, nullptr, nullptr, nullptr, nullptr);
    k_att<<<NPAIRS / 8, 256>>>(w_att, b_att, idx_j);
    k_exp<<<(NPAIRS + 255) / 256, 256>>>(idx_j);
    k_scan<<<1, 1024>>>();
    k_fill<<<(NPAIRS + 255) / 256, 256>>>(idx_j);
    k_gemm<3><<<dim3(NPAIRS / 64, 4), 256>>>(w_mix, nullptr, nullptr, nullptr, nullptr, idx_j, nullptr);
    k_segreduce<<<NATOMS / 8, 256>>>(q, r_ij, d_ij);
    k_gemm<4><<<157, 256>>>(w_post1, b_post1, nullptr, nullptr, nullptr, nullptr, nullptr);
    k_gemm<5><<<157, 256>>>(w_post2, b_post2, nullptr, nullptr, nullptr, nullptr, nullptr);
    k_gemm<6><<<157, 256>>>(w_node1, b_node1, nullptr, nullptr, nullptr, nullptr, nullptr);
    k_gemm<7><<<157, 256>>>(w_node2, b_node2, q, nullptr, nullptr, nullptr, out);
}

// round 8
// speedup vs baseline: 1.0014x; 1.0014x over previous
#include <cuda_runtime.h>
#include <float.h>

#define NATOMS 10000
#define NPAIRS 160000
#define HPITCH 192   // padded h row: [q0(128) | filtered(50) | d(1) | zero pad(13)]

// ---------------- scratch (device globals; no allocation allowed) ----------------
__device__ float g_h[(size_t)NPAIRS * HPITCH];     // edge feature rows
__device__ float g_hidden[(size_t)NPAIRS * 64];
__device__ float g_m[(size_t)NPAIRS * 64];         // q_ij_mtx
__device__ float g_att[(size_t)NPAIRS * 4];
__device__ float g_e[(size_t)NPAIRS * 4];
__device__ float g_segmax[NATOMS * 4];
__device__ float g_denom[NATOMS * 4];
__device__ int   g_counts[NATOMS];
__device__ int   g_cursor[NATOMS];
__device__ int   g_offs[NATOMS + 1];
__device__ int   g_order[NPAIRS];
__device__ float g_coeffs[(size_t)NPAIRS * 256];
__device__ float g_norm[(size_t)NATOMS * 256];
__device__ float g_h2[(size_t)NATOMS * 384];       // [q(64) | q_ij(256) | q_comb(64)]
__device__ float g_t1[(size_t)NATOMS * 64];
__device__ float g_t2[(size_t)NATOMS * 64];

// ---------------- helpers ----------------
__device__ __forceinline__ float siluf(float x) { return x / (1.f + __expf(-x)); }
__device__ __forceinline__ float fast_tanh(float x) {
    return 1.f - 2.f / (__expf(2.f * x) + 1.f);
}
__device__ __forceinline__ void atomicMaxFloat(float* a, float v) {
    if (v >= 0.f) atomicMax((int*)a, __float_as_int(v));
    else          atomicMin((unsigned int*)a, __float_as_uint(v));
}

// ---------------- init ----------------
__global__ void k_init() {
    int i = blockIdx.x * blockDim.x + threadIdx.x;
    if (i < NATOMS * 4) { g_segmax[i] = -FLT_MAX; g_denom[i] = 0.f; }
    if (i < NATOMS)     { g_counts[i] = 0; g_cursor[i] = 0; }
}

// ---------------- gather: build q0 | d | zero-pad rows of g_h ----------------
__global__ void k_gather(const float* __restrict__ q, const int* __restrict__ idx_i,
                         const int* __restrict__ idx_j, const float* __restrict__ d_ij) {
    int p    = blockIdx.x * 8 + (threadIdx.x >> 5);
    int lane = threadIdx.x & 31;
    int i = idx_i[p], j = idx_j[p];
    float* hr = g_h + (size_t)p * HPITCH;
    const float* qi = q + (size_t)i * 64;
    const float* qj = q + (size_t)j * 64;
    hr[lane]      = qi[lane];       hr[32 + lane] = qi[32 + lane];
    hr[64 + lane] = qj[lane];       hr[96 + lane] = qj[32 + lane];
    if (lane < 14) hr[178 + lane] = (lane == 0) ? d_ij[p] : 0.f;
}

// ---------------- generic tiled GEMM: C = epi(A @ W^T + b) ----------------
// BM=64, BN=64, BK=16, 256 threads, 4x4 register tile per thread.
// MODE 0: h[:, :128] @ w_in^T,  epi: rbf * (.)  -> writes g_h cols 128..177
// MODE 1: h @ w_out1^T, silu -> g_hidden
// MODE 2: hidden @ w_out2^T, +bias -> g_m
// MODE 3: (m x comb outer) @ w_mix^T, tanh -> g_coeffs   (A built on the fly)
// MODE 4: norm @ w_post1^T, silu -> g_t1
// MODE 5: t1 @ w_post2^T, silu -> g_h2[:, 320:384]
// MODE 6: h2 @ w_node1^T, silu -> g_t2
// MODE 7: t2 @ w_node2^T, q + silu(.) -> out
template <int MODE>
__global__ void k_gemm(const float* __restrict__ W, const float* __restrict__ bias,
                       const float* __restrict__ x1, const float* __restrict__ x2,
                       const float* __restrict__ x3, const int* __restrict__ xi,
                       float* __restrict__ outp) {
    constexpr int M  = (MODE <= 3) ? NPAIRS : NATOMS;
    constexpr int KT = (MODE == 0) ? 8  : (MODE == 1) ? 12 : (MODE == 2) ? 4 :
                       (MODE == 3) ? 16 : (MODE == 4) ? 16 : (MODE == 5) ? 4 :
                       (MODE == 6) ? 24 : 4;
    constexpr int KW = (MODE == 0) ? 128 : (MODE == 1) ? 179 : (MODE == 2) ? 64 :
                       (MODE == 3) ? 256 : (MODE == 4) ? 256 : (MODE == 5) ? 64 :
                       (MODE == 6) ? 384 : 64;
    constexpr int NW  = (MODE == 3) ? 256 : (MODE == 0) ? 50 : 64;
    constexpr int LDA = (MODE <= 1) ? HPITCH : (MODE == 4) ? 256 : (MODE == 6) ? 384 : 64;
    constexpr int LDC = (MODE == 0) ? HPITCH : (MODE == 3) ? 256 : (MODE == 5) ? 384 : 64;

    const float* A = nullptr;
    float* C = nullptr;
    if constexpr (MODE == 0)      { A = g_h;      C = g_h + 128; }
    else if constexpr (MODE == 1) { A = g_h;      C = g_hidden;  }
    else if constexpr (MODE == 2) { A = g_hidden; C = g_m;       }
    else if constexpr (MODE == 3) {               C = g_coeffs;  }
    else if constexpr (MODE == 4) { A = g_norm;   C = g_t1;      }
    else if constexpr (MODE == 5) { A = g_t1;     C = g_h2 + 320;}
    else if constexpr (MODE == 6) { A = g_h2;     C = g_t2;      }
    else                          { A = g_t2;     C = outp;      }

    __shared__ __align__(16) float sA[16 * 68];
    __shared__ __align__(16) float sW[16 * 68];

    int t  = threadIdx.x;
    int p0 = blockIdx.x * 64;
    int nb = (MODE == 3) ? blockIdx.y : 0;
    int tx = t & 15, ty = t >> 4;

    int am   = t >> 2;          // staging row within tile (A rows / W rows)
    int ak   = (t & 3) * 4;     // staging k offset (float4)
    int arow = p0 + am;

    float4 comb = make_float4(0.f, 0.f, 0.f, 0.f);
    const float* mrow = nullptr;
    if constexpr (MODE == 3) {
        if (arow < M) {
            int jj = xi[arow];
            comb.x = g_e[arow * 4 + 0] / g_denom[jj * 4 + 0];
            comb.y = g_e[arow * 4 + 1] / g_denom[jj * 4 + 1];
            comb.z = g_e[arow * 4 + 2] / g_denom[jj * 4 + 2];
            comb.w = g_e[arow * 4 + 3] / g_denom[jj * 4 + 3];
            mrow = g_m + (size_t)arow * 64;
        }
    }

    float acc[4][4];
#pragma unroll
    for (int i = 0; i < 4; i++)
#pragma unroll
        for (int j = 0; j < 4; j++) acc[i][j] = 0.f;

    for (int kt = 0; kt < KT; kt++) {
        int k0 = kt * 16;
        // fetch A fragment
        float4 av = make_float4(0.f, 0.f, 0.f, 0.f);
        if constexpr (MODE == 3) {
            if (arow < M) {
                float mv = __ldg(&mrow[(k0 >> 2) + (t & 3)]);  // k = k0+ak+j -> f = k>>2
                av.x = mv * comb.x; av.y = mv * comb.y;
                av.z = mv * comb.z; av.w = mv * comb.w;
            }
        } else {
            if (arow < M)
                av = *reinterpret_cast<const float4*>(A + (size_t)arow * LDA + k0 + ak);
        }
        // fetch W fragment (scalar, zero-padded)
        int gnW = nb * 64 + am;
        float wv[4];
#pragma unroll
        for (int j = 0; j < 4; j++) {
            int k = k0 + ak + j;
            wv[j] = (gnW < NW && k < KW) ? __ldg(&W[(size_t)gnW * KW + k]) : 0.f;
        }
        __syncthreads();
        sA[(ak + 0) * 68 + am] = av.x; sA[(ak + 1) * 68 + am] = av.y;
        sA[(ak + 2) * 68 + am] = av.z; sA[(ak + 3) * 68 + am] = av.w;
#pragma unroll
        for (int j = 0; j < 4; j++) sW[(ak + j) * 68 + am] = wv[j];
        __syncthreads();
#pragma unroll
        for (int kk = 0; kk < 16; kk++) {
            float4 a = *reinterpret_cast<const float4*>(&sA[kk * 68 + ty * 4]);
            float4 b = *reinterpret_cast<const float4*>(&sW[kk * 68 + tx * 4]);
            acc[0][0] += a.x * b.x; acc[0][1] += a.x * b.y; acc[0][2] += a.x * b.z; acc[0][3] += a.x * b.w;
            acc[1][0] += a.y * b.x; acc[1][1] += a.y * b.y; acc[1][2] += a.y * b.z; acc[1][3] += a.y * b.w;
            acc[2][0] += a.z * b.x; acc[2][1] += a.z * b.y; acc[2][2] += a.z * b.z; acc[2][3] += a.z * b.w;
            acc[3][0] += a.w * b.x; acc[3][1] += a.w * b.y; acc[3][2] += a.w * b.z; acc[3][3] += a.w * b.w;
        }
    }

#pragma unroll
    for (int i = 0; i < 4; i++) {
        int p = p0 + ty * 4 + i;
        if (p >= M) continue;
        float dv = 0.f;
        if constexpr (MODE == 0) dv = x1[p];
#pragma unroll
        for (int j = 0; j < 4; j++) {
            int gn = nb * 64 + tx * 4 + j;
            float v = acc[i][j];
            if constexpr (MODE == 0) {
                if (gn < 50) {
                    float off = x2[gn], wd = x3[gn];
                    float dd = dv - off;
                    float r = __expf((-0.5f / (wd * wd)) * dd * dd);
                    C[(size_t)p * LDC + gn] = r * (v + bias[gn]);
                }
            } else if constexpr (MODE == 2) {
                C[(size_t)p * LDC + gn] = v + bias[gn];
            } else if constexpr (MODE == 3) {
                C[(size_t)p * LDC + gn] = fast_tanh(v);
            } else if constexpr (MODE == 7) {
                C[(size_t)p * LDC + gn] = x1[(size_t)p * 64 + gn] + siluf(v + bias[gn]);
            } else {
                C[(size_t)p * LDC + gn] = siluf(v + bias[gn]);
            }
        }
    }
}

// ---------------- attention logits + segment max + degree counts ----------------
__global__ void k_att(const float* __restrict__ w_att, const float* __restrict__ b_att,
                      const int* __restrict__ idx_j) {
    int p    = blockIdx.x * 8 + (threadIdx.x >> 5);
    int lane = threadIdx.x & 31;
    const float* mr = g_m + (size_t)p * 64;
    float m1 = mr[lane], m2 = mr[32 + lane];
    float pa[4];
#pragma unroll
    for (int a = 0; a < 4; a++)
        pa[a] = __ldg(&w_att[a * 64 + lane]) * m1 + __ldg(&w_att[a * 64 + 32 + lane]) * m2;
#pragma unroll
    for (int o = 16; o > 0; o >>= 1)
#pragma unroll
        for (int a = 0; a < 4; a++) pa[a] += __shfl_xor_sync(0xffffffffu, pa[a], o);
    if (lane == 0) {
        int j = idx_j[p];
#pragma unroll
        for (int a = 0; a < 4; a++) {
            float v = pa[a] + b_att[a];
            v = (v >= 0.f) ? v : 2.f * expm1f(0.5f * v);   // celu alpha=2
            g_att[p * 4 + a] = v;
            atomicMaxFloat(&g_segmax[j * 4 + a], v);
        }
        atomicAdd(&g_counts[j], 1);
    }
}

// ---------------- softmax numerators + denominators ----------------
__global__ void k_exp(const int* __restrict__ idx_j) {
    int p = blockIdx.x * blockDim.x + threadIdx.x;
    if (p >= NPAIRS) return;
    int j = idx_j[p];
#pragma unroll
    for (int a = 0; a < 4; a++) {
        float v = __expf(g_att[p * 4 + a] - g_segmax[j * 4 + a]);
        g_e[p * 4 + a] = v;
        atomicAdd(&g_denom[j * 4 + a], v);
    }
}

// ---------------- exclusive scan of counts -> offs (single block) ----------------
__global__ void k_scan() {
    __shared__ int part[1024];
    int tid = threadIdx.x;
    int base = tid * 10;
    int loc[10];
    int s = 0;
#pragma unroll
    for (int j = 0; j < 10; j++) {
        int idx = base + j;
        int v = (idx < NATOMS) ? g_counts[idx] : 0;
        loc[j] = s; s += v;
    }
    part[tid] = s;
    __syncthreads();
    for (int off = 1; off < 1024; off <<= 1) {
        int v = (tid >= off) ? part[tid - off] : 0;
        __syncthreads();
        part[tid] += v;
        __syncthreads();
    }
    int pre = (tid > 0) ? part[tid - 1] : 0;
#pragma unroll
    for (int j = 0; j < 10; j++) {
        int idx = base + j;
        if (idx < NATOMS) g_offs[idx] = pre + loc[j];
    }
    if (tid == 1023) g_offs[NATOMS] = part[1023];
}

// ---------------- fill CSR edge order ----------------
__global__ void k_fill(const int* __restrict__ idx_j) {
    int p = blockIdx.x * blockDim.x + threadIdx.x;
    if (p >= NPAIRS) return;
    int j = idx_j[p];
    int pos = atomicAdd(&g_cursor[j], 1);
    g_order[g_offs[j] + pos] = p;
}

// ---------------- per-atom gather reductions: q_ij, norm; also copy q into h2 ----
__global__ void k_segreduce(const float* __restrict__ q, const float* __restrict__ r_ij,
                            const float* __restrict__ d_ij) {
    int n    = blockIdx.x * 8 + (threadIdx.x >> 5);
    int lane = threadIdx.x & 31;
    if (n >= NATOMS) return;
    int beg = g_offs[n], end = g_offs[n + 1];
    int cnt = end - beg;
    float inv = 1.f / (float)max(cnt, 1);
    g_h2[(size_t)n * 384 + lane]      = q[(size_t)n * 64 + lane];
    g_h2[(size_t)n * 384 + 32 + lane] = q[(size_t)n * 64 + 32 + lane];
    for (int cr = 0; cr < 8; cr++) {
        int c = cr * 32 + lane;
        int f = c >> 2, hh = c & 3;
        float invd = 1.f / g_denom[n * 4 + hh];   // unused when cnt==0
        float ax = 0.f, ay = 0.f, az = 0.f, aq = 0.f;
        for (int tt = beg; tt < end; tt++) {
            int p = g_order[tt];
            float co   = __ldg(&g_coeffs[(size_t)p * 256 + c]);
            float rinv = 1.f / (__ldg(&d_ij[p]) + 1e-5f);
            ax += co * __ldg(&r_ij[p * 3 + 0]) * rinv;
            ay += co * __ldg(&r_ij[p * 3 + 1]) * rinv;
            az += co * __ldg(&r_ij[p * 3 + 2]) * rinv;
            aq += __ldg(&g_m[(size_t)p * 64 + f]) * __ldg(&g_e[p * 4 + hh]) * invd;
        }
        float mx = ax * inv, my = ay * inv, mz = az * inv;
        g_norm[(size_t)n * 256 + c]     = mx * mx + my * my + mz * mz;
        g_h2[(size_t)n * 384 + 64 + c]  = aq;
    }
}

// ---------------- launch ----------------
extern "C" void kernel_launch(void* const* d_in, const int* in_sizes, int n_in,
                              void* d_out, int out_size) {
    (void)in_sizes; (void)n_in; (void)out_size;
    const float* q       = (const float*)d_in[0];
    const float* r_ij    = (const float*)d_in[2];
    const float* d_ij    = (const float*)d_in[3];
    const int*   idx_i   = (const int*)d_in[4];
    const int*   idx_j   = (const int*)d_in[5];
    const float* rbf_off = (const float*)d_in[6];
    const float* rbf_w   = (const float*)d_in[7];
    const float* w_in    = (const float*)d_in[8];
    const float* b_in    = (const float*)d_in[9];
    const float* w_out1  = (const float*)d_in[10];
    const float* b_out1  = (const float*)d_in[11];
    const float* w_out2  = (const float*)d_in[12];
    const float* b_out2  = (const float*)d_in[13];
    const float* w_att   = (const float*)d_in[14];
    const float* b_att   = (const float*)d_in[15];
    const float* w_mix   = (const float*)d_in[16];
    const float* w_post1 = (const float*)d_in[17];
    const float* b_post1 = (const float*)d_in[18];
    const float* w_post2 = (const float*)d_in[19];
    const float* b_post2 = (const float*)d_in[20];
    const float* w_node1 = (const float*)d_in[21];
    const float* b_node1 = (const float*)d_in[22];
    const float* w_node2 = (const float*)d_in[23];
    const float* b_node2 = (const float*)d_in[24];
    float* out = (float*)d_out;

    k_init<<<157, 256>>>();
    k_gather<<<NPAIRS / 8, 256>>>(q, idx_i, idx_j, d_ij);
    k_gemm<0><<<NPAIRS / 64, 256>>>(w_in, b_in, d_ij, rbf_off, rbf_w, nullptr, nullptr);
    k_gemm<1><<<NPAIRS / 64, 256>>>(w_out1, b_out1, nullptr, nullptr, nullptr, nullptr, nullptr);
    k_gemm<2><<<NPAIRS / 64, 256>>>(w_out2, b_out2, nullptr, nullptr, nullptr, nullptr, nullptr);
    k_att<<<NPAIRS / 8, 256>>>(w_att, b_att, idx_j);
    k_exp<<<(NPAIRS + 255) / 256, 256>>>(idx_j);
    k_scan<<<1, 1024>>>();
    k_fill<<<(NPAIRS + 255) / 256, 256>>>(idx_j);
    k_gemm<3><<<dim3(NPAIRS / 64, 4), 256>>>(w_mix, nullptr, nullptr, nullptr, nullptr, idx_j, nullptr);
    k_segreduce<<<NATOMS / 8, 256>>>(q, r_ij, d_ij);
    k_gemm<4><<<157, 256>>>(w_post1, b_post1, nullptr, nullptr, nullptr, nullptr, nullptr);
    k_gemm<5><<<157, 256>>>(w_post2, b_post2, nullptr, nullptr, nullptr, nullptr, nullptr);
    k_gemm<6><<<157, 256>>>(w_node1, b_node1, nullptr, nullptr, nullptr, nullptr, nullptr);
    k_gemm<7><<<157, 256>>>(w_node2, b_node2, q, nullptr, nullptr, nullptr, out);
}

// round 9
// speedup vs baseline: 1.1071x; 1.1056x over previous
#include <cuda_runtime.h>
#include <float.h>

#define NATOMS 10000
#define NPAIRS 160000
#define HPITCH 192   // padded h row: [q0(128) | filtered(50) | d(1) | zero pad(13)]

// ---------------- scratch (device globals; no allocation allowed) ----------------
__device__ float g_h[(size_t)NPAIRS * HPITCH];     // edge feature rows
__device__ float g_hidden[(size_t)NPAIRS * 64];
__device__ float g_m[(size_t)NPAIRS * 64];         // q_ij_mtx
__device__ float g_att[(size_t)NPAIRS * 4];
__device__ float g_e[(size_t)NPAIRS * 4];
__device__ float g_segmax[NATOMS * 4];
__device__ float g_denom[NATOMS * 4];
__device__ int   g_counts[NATOMS];
__device__ int   g_cursor[NATOMS];
__device__ int   g_offs[NATOMS + 1];
__device__ int   g_order[NPAIRS];
__device__ float g_coeffs[(size_t)NPAIRS * 256];
__device__ float g_norm[(size_t)NATOMS * 256];
__device__ float g_h2[(size_t)NATOMS * 384];       // [q(64) | q_ij(256) | q_comb(64)]
__device__ float g_t1[(size_t)NATOMS * 64];
__device__ float g_t2[(size_t)NATOMS * 64];

// ---------------- helpers ----------------
__device__ __forceinline__ float siluf(float x) { return x / (1.f + __expf(-x)); }
__device__ __forceinline__ float fast_tanh(float x) {
    return 1.f - 2.f / (__expf(2.f * x) + 1.f);
}
__device__ __forceinline__ void atomicMaxFloat(float* a, float v) {
    if (v >= 0.f) atomicMax((int*)a, __float_as_int(v));
    else          atomicMin((unsigned int*)a, __float_as_uint(v));
}

// ---------------- init ----------------
__global__ void k_init() {
    int i = blockIdx.x * blockDim.x + threadIdx.x;
    if (i < NATOMS * 4) { g_segmax[i] = -FLT_MAX; g_denom[i] = 0.f; }
    if (i < NATOMS)     { g_counts[i] = 0; g_cursor[i] = 0; }
}

// ---------------- gather: build q0 | d | zero-pad rows of g_h ----------------
__global__ void k_gather(const float* __restrict__ q, const int* __restrict__ idx_i,
                         const int* __restrict__ idx_j, const float* __restrict__ d_ij) {
    int p    = blockIdx.x * 8 + (threadIdx.x >> 5);
    int lane = threadIdx.x & 31;
    int i = idx_i[p], j = idx_j[p];
    float* hr = g_h + (size_t)p * HPITCH;
    const float* qi = q + (size_t)i * 64;
    const float* qj = q + (size_t)j * 64;
    hr[lane]      = qi[lane];       hr[32 + lane] = qi[32 + lane];
    hr[64 + lane] = qj[lane];       hr[96 + lane] = qj[32 + lane];
    if (lane < 14) hr[178 + lane] = (lane == 0) ? d_ij[p] : 0.f;
}

// ================= pair-level GEMM, fat tiles =================
// BM=256, BN=64, BK=16, 256 threads, 8x8 register micro-tile per thread.
// MODE 0: h[:, :128] @ w_in^T,  epi: rbf * (.)  -> writes g_h cols 128..177
// MODE 1: h @ w_out1^T, silu -> g_hidden
// MODE 2: hidden @ w_out2^T, +bias -> g_m
// MODE 3: (m x comb outer) @ w_mix^T, tanh -> g_coeffs   (A built on the fly; grid.y=4)
template <int MODE>
__global__ void __launch_bounds__(256, 2)
k_gemm2(const float* __restrict__ W, const float* __restrict__ bias,
        const float* __restrict__ d_ij, const float* __restrict__ roffs,
        const float* __restrict__ rwids, const int* __restrict__ xi) {
    constexpr int KT  = (MODE == 0) ? 8 : (MODE == 1) ? 12 : (MODE == 2) ? 4 : 16;
    constexpr int KW  = (MODE == 0) ? 128 : (MODE == 1) ? 179 : (MODE == 2) ? 64 : 256;
    constexpr int NW  = (MODE == 0) ? 50 : 64;   // valid W rows within this block's 64
    constexpr int LDA = (MODE <= 1) ? HPITCH : 64;
    constexpr int LDC = (MODE == 0) ? HPITCH : (MODE == 3) ? 256 : 64;

    const float* A = (MODE == 2) ? g_hidden : g_h;
    float* C = (MODE == 0) ? (g_h + 128) : (MODE == 1) ? g_hidden :
               (MODE == 2) ? g_m : g_coeffs;

    __shared__ __align__(16) float sA[16 * 256];  // [k][m]
    __shared__ __align__(16) float sW[16 * 68];   // [k][n]

    const int t  = threadIdx.x;
    const int p0 = blockIdx.x * 256;
    const int nb = (MODE == 3) ? blockIdx.y : 0;
    const int tx = t & 7;        // 8 col-groups of 8
    const int ty = t >> 3;       // 32 row-groups of 8
    const int arow = p0 + t;     // staging: one A row per thread (always < NPAIRS)
    const int wr = t >> 2;       // staging: W row 0..63
    const int wk = (t & 3) * 4;  // staging: k offset
    const size_t wbase = (size_t)(nb * 64 + wr) * KW;

    float4 comb = make_float4(0.f, 0.f, 0.f, 0.f);
    const float* mrow = nullptr;
    if constexpr (MODE == 3) {
        int jj = xi[arow];
        float4 e4 = *reinterpret_cast<const float4*>(&g_e[(size_t)arow * 4]);
        float4 d4 = *reinterpret_cast<const float4*>(&g_denom[(size_t)jj * 4]);
        comb = make_float4(e4.x / d4.x, e4.y / d4.y, e4.z / d4.z, e4.w / d4.w);
        mrow = g_m + (size_t)arow * 64;
    }

    float acc[8][8];
#pragma unroll
    for (int i = 0; i < 8; i++)
#pragma unroll
        for (int j = 0; j < 8; j++) acc[i][j] = 0.f;

    float4 pa0, pa1, pa2, pa3;
    float pw[4];

    // ---- prefetch tile 0 ----
    {
        if constexpr (MODE == 3) {
            pa0 = *reinterpret_cast<const float4*>(mrow);
        } else {
            const float* ap = A + (size_t)arow * LDA;
            pa0 = *reinterpret_cast<const float4*>(ap + 0);
            pa1 = *reinterpret_cast<const float4*>(ap + 4);
            pa2 = *reinterpret_cast<const float4*>(ap + 8);
            pa3 = *reinterpret_cast<const float4*>(ap + 12);
        }
#pragma unroll
        for (int j = 0; j < 4; j++) {
            int k = wk + j;
            bool ok = true;
            if constexpr (NW < 64) ok = (wr < NW);
            if constexpr ((KW & 15) != 0) ok = ok && (k < KW);
            pw[j] = ok ? __ldg(&W[wbase + k]) : 0.f;
        }
    }

    for (int kt = 0; kt < KT; kt++) {
        __syncthreads();
        // ---- store staged fragments ----
        if constexpr (MODE == 3) {
            float mv[4] = {pa0.x, pa0.y, pa0.z, pa0.w};
            float cb[4] = {comb.x, comb.y, comb.z, comb.w};
#pragma unroll
            for (int f = 0; f < 4; f++)
#pragma unroll
                for (int h = 0; h < 4; h++)
                    sA[(f * 4 + h) * 256 + t] = mv[f] * cb[h];
        } else {
            sA[(0) * 256 + t] = pa0.x; sA[(1) * 256 + t] = pa0.y;
            sA[(2) * 256 + t] = pa0.z; sA[(3) * 256 + t] = pa0.w;
            sA[(4) * 256 + t] = pa1.x; sA[(5) * 256 + t] = pa1.y;
            sA[(6) * 256 + t] = pa1.z; sA[(7) * 256 + t] = pa1.w;
            sA[(8) * 256 + t] = pa2.x; sA[(9) * 256 + t] = pa2.y;
            sA[(10) * 256 + t] = pa2.z; sA[(11) * 256 + t] = pa2.w;
            sA[(12) * 256 + t] = pa3.x; sA[(13) * 256 + t] = pa3.y;
            sA[(14) * 256 + t] = pa3.z; sA[(15) * 256 + t] = pa3.w;
        }
#pragma unroll
        for (int j = 0; j < 4; j++) sW[(wk + j) * 68 + wr] = pw[j];
        __syncthreads();

        // ---- prefetch next tile into registers (overlaps with FFMAs) ----
        if (kt + 1 < KT) {
            int k0 = (kt + 1) * 16;
            if constexpr (MODE == 3) {
                pa0 = *reinterpret_cast<const float4*>(mrow + (kt + 1) * 4);
            } else {
                const float* ap = A + (size_t)arow * LDA + k0;
                pa0 = *reinterpret_cast<const float4*>(ap + 0);
                pa1 = *reinterpret_cast<const float4*>(ap + 4);
                pa2 = *reinterpret_cast<const float4*>(ap + 8);
                pa3 = *reinterpret_cast<const float4*>(ap + 12);
            }
#pragma unroll
            for (int j = 0; j < 4; j++) {
                int k = k0 + wk + j;
                bool ok = true;
                if constexpr (NW < 64) ok = (wr < NW);
                if constexpr ((KW & 15) != 0) ok = ok && (k < KW);
                pw[j] = ok ? __ldg(&W[wbase + k]) : 0.f;
            }
        }

        // ---- 16x (8x8) FFMA ----
#pragma unroll
        for (int kk = 0; kk < 16; kk++) {
            float4 a0 = *reinterpret_cast<const float4*>(&sA[kk * 256 + ty * 8]);
            float4 a1 = *reinterpret_cast<const float4*>(&sA[kk * 256 + ty * 8 + 4]);
            float4 b0 = *reinterpret_cast<const float4*>(&sW[kk * 68 + tx * 8]);
            float4 b1 = *reinterpret_cast<const float4*>(&sW[kk * 68 + tx * 8 + 4]);
            float av[8] = {a0.x, a0.y, a0.z, a0.w, a1.x, a1.y, a1.z, a1.w};
            float bv[8] = {b0.x, b0.y, b0.z, b0.w, b1.x, b1.y, b1.z, b1.w};
#pragma unroll
            for (int i = 0; i < 8; i++)
#pragma unroll
                for (int j = 0; j < 8; j++)
                    acc[i][j] += av[i] * bv[j];
        }
    }

    // ---- epilogue ----
    if constexpr (MODE == 0) {
#pragma unroll
        for (int i = 0; i < 8; i++) {
            int p = p0 + ty * 8 + i;
            float dv = __ldg(&d_ij[p]);
#pragma unroll
            for (int j = 0; j < 8; j++) {
                int gn = tx * 8 + j;
                if (gn < 50) {
                    float off = __ldg(&roffs[gn]), wd = __ldg(&rwids[gn]);
                    float dd = dv - off;
                    float r = __expf((-0.5f / (wd * wd)) * dd * dd);
                    C[(size_t)p * LDC + gn] = r * (acc[i][j] + __ldg(&bias[gn]));
                }
            }
        }
    } else if constexpr (MODE == 3) {
#pragma unroll
        for (int i = 0; i < 8; i++) {
            int p = p0 + ty * 8 + i;
            float4 v0, v1;
            v0.x = fast_tanh(acc[i][0]); v0.y = fast_tanh(acc[i][1]);
            v0.z = fast_tanh(acc[i][2]); v0.w = fast_tanh(acc[i][3]);
            v1.x = fast_tanh(acc[i][4]); v1.y = fast_tanh(acc[i][5]);
            v1.z = fast_tanh(acc[i][6]); v1.w = fast_tanh(acc[i][7]);
            float* cp = C + (size_t)p * 256 + nb * 64 + tx * 8;
            *reinterpret_cast<float4*>(cp)     = v0;
            *reinterpret_cast<float4*>(cp + 4) = v1;
        }
    } else {
        float bb[8];
#pragma unroll
        for (int j = 0; j < 8; j++) bb[j] = __ldg(&bias[tx * 8 + j]);
#pragma unroll
        for (int i = 0; i < 8; i++) {
            int p = p0 + ty * 8 + i;
            float4 v0, v1;
            if constexpr (MODE == 2) {
                v0.x = acc[i][0] + bb[0]; v0.y = acc[i][1] + bb[1];
                v0.z = acc[i][2] + bb[2]; v0.w = acc[i][3] + bb[3];
                v1.x = acc[i][4] + bb[4]; v1.y = acc[i][5] + bb[5];
                v1.z = acc[i][6] + bb[6]; v1.w = acc[i][7] + bb[7];
            } else {
                v0.x = siluf(acc[i][0] + bb[0]); v0.y = siluf(acc[i][1] + bb[1]);
                v0.z = siluf(acc[i][2] + bb[2]); v0.w = siluf(acc[i][3] + bb[3]);
                v1.x = siluf(acc[i][4] + bb[4]); v1.y = siluf(acc[i][5] + bb[5]);
                v1.z = siluf(acc[i][6] + bb[6]); v1.w = siluf(acc[i][7] + bb[7]);
            }
            float* cp = C + (size_t)p * 64 + tx * 8;
            *reinterpret_cast<float4*>(cp)     = v0;
            *reinterpret_cast<float4*>(cp + 4) = v1;
        }
    }
}

// ================= atom-level GEMM (small M): original 64x64 tiles =================
// MODE 4: norm @ w_post1^T, silu -> g_t1
// MODE 5: t1 @ w_post2^T, silu -> g_h2[:, 320:384]
// MODE 6: h2 @ w_node1^T, silu -> g_t2
// MODE 7: t2 @ w_node2^T, q + silu(.) -> out
template <int MODE>
__global__ void k_gemm(const float* __restrict__ W, const float* __restrict__ bias,
                       const float* __restrict__ x1, float* __restrict__ outp) {
    constexpr int M  = NATOMS;
    constexpr int KT = (MODE == 4) ? 16 : (MODE == 5) ? 4 : (MODE == 6) ? 24 : 4;
    constexpr int KW = (MODE == 4) ? 256 : (MODE == 5) ? 64 : (MODE == 6) ? 384 : 64;
    constexpr int LDA = (MODE == 4) ? 256 : (MODE == 6) ? 384 : 64;
    constexpr int LDC = (MODE == 5) ? 384 : 64;

    const float* A;
    float* C;
    if constexpr (MODE == 4)      { A = g_norm;   C = g_t1;      }
    else if constexpr (MODE == 5) { A = g_t1;     C = g_h2 + 320;}
    else if constexpr (MODE == 6) { A = g_h2;     C = g_t2;      }
    else                          { A = g_t2;     C = outp;      }

    __shared__ __align__(16) float sA[16 * 68];
    __shared__ __align__(16) float sW[16 * 68];

    int t  = threadIdx.x;
    int p0 = blockIdx.x * 64;
    int tx = t & 15, ty = t >> 4;
    int am   = t >> 2;
    int ak   = (t & 3) * 4;
    int arow = p0 + am;

    float acc[4][4];
#pragma unroll
    for (int i = 0; i < 4; i++)
#pragma unroll
        for (int j = 0; j < 4; j++) acc[i][j] = 0.f;

    for (int kt = 0; kt < KT; kt++) {
        int k0 = kt * 16;
        float4 av = make_float4(0.f, 0.f, 0.f, 0.f);
        if (arow < M)
            av = *reinterpret_cast<const float4*>(A + (size_t)arow * LDA + k0 + ak);
        float wv[4];
#pragma unroll
        for (int j = 0; j < 4; j++) {
            int k = k0 + ak + j;
            wv[j] = (k < KW) ? __ldg(&W[(size_t)am * KW + k]) : 0.f;
        }
        __syncthreads();
        sA[(ak + 0) * 68 + am] = av.x; sA[(ak + 1) * 68 + am] = av.y;
        sA[(ak + 2) * 68 + am] = av.z; sA[(ak + 3) * 68 + am] = av.w;
#pragma unroll
        for (int j = 0; j < 4; j++) sW[(ak + j) * 68 + am] = wv[j];
        __syncthreads();
#pragma unroll
        for (int kk = 0; kk < 16; kk++) {
            float4 a = *reinterpret_cast<const float4*>(&sA[kk * 68 + ty * 4]);
            float4 b = *reinterpret_cast<const float4*>(&sW[kk * 68 + tx * 4]);
            acc[0][0] += a.x * b.x; acc[0][1] += a.x * b.y; acc[0][2] += a.x * b.z; acc[0][3] += a.x * b.w;
            acc[1][0] += a.y * b.x; acc[1][1] += a.y * b.y; acc[1][2] += a.y * b.z; acc[1][3] += a.y * b.w;
            acc[2][0] += a.z * b.x; acc[2][1] += a.z * b.y; acc[2][2] += a.z * b.z; acc[2][3] += a.z * b.w;
            acc[3][0] += a.w * b.x; acc[3][1] += a.w * b.y; acc[3][2] += a.w * b.z; acc[3][3] += a.w * b.w;
        }
    }

#pragma unroll
    for (int i = 0; i < 4; i++) {
        int p = p0 + ty * 4 + i;
        if (p >= M) continue;
#pragma unroll
        for (int j = 0; j < 4; j++) {
            int gn = tx * 4 + j;
            float v = acc[i][j];
            if constexpr (MODE == 7) {
                C[(size_t)p * LDC + gn] = x1[(size_t)p * 64 + gn] + siluf(v + bias[gn]);
            } else {
                C[(size_t)p * LDC + gn] = siluf(v + bias[gn]);
            }
        }
    }
}

// ---------------- attention logits + segment max + degree counts ----------------
__global__ void k_att(const float* __restrict__ w_att, const float* __restrict__ b_att,
                      const int* __restrict__ idx_j) {
    int p    = blockIdx.x * 8 + (threadIdx.x >> 5);
    int lane = threadIdx.x & 31;
    const float* mr = g_m + (size_t)p * 64;
    float m1 = mr[lane], m2 = mr[32 + lane];
    float pa[4];
#pragma unroll
    for (int a = 0; a < 4; a++)
        pa[a] = __ldg(&w_att[a * 64 + lane]) * m1 + __ldg(&w_att[a * 64 + 32 + lane]) * m2;
#pragma unroll
    for (int o = 16; o > 0; o >>= 1)
#pragma unroll
        for (int a = 0; a < 4; a++) pa[a] += __shfl_xor_sync(0xffffffffu, pa[a], o);
    if (lane == 0) {
        int j = idx_j[p];
#pragma unroll
        for (int a = 0; a < 4; a++) {
            float v = pa[a] + b_att[a];
            v = (v >= 0.f) ? v : 2.f * expm1f(0.5f * v);   // celu alpha=2
            g_att[p * 4 + a] = v;
            atomicMaxFloat(&g_segmax[j * 4 + a], v);
        }
        atomicAdd(&g_counts[j], 1);
    }
}

// ---------------- softmax numerators + denominators ----------------
__global__ void k_exp(const int* __restrict__ idx_j) {
    int p = blockIdx.x * blockDim.x + threadIdx.x;
    if (p >= NPAIRS) return;
    int j = idx_j[p];
#pragma unroll
    for (int a = 0; a < 4; a++) {
        float v = __expf(g_att[p * 4 + a] - g_segmax[j * 4 + a]);
        g_e[p * 4 + a] = v;
        atomicAdd(&g_denom[j * 4 + a], v);
    }
}

// ---------------- exclusive scan of counts -> offs (single block) ----------------
__global__ void k_scan() {
    __shared__ int part[1024];
    int tid = threadIdx.x;
    int base = tid * 10;
    int loc[10];
    int s = 0;
#pragma unroll
    for (int j = 0; j < 10; j++) {
        int idx = base + j;
        int v = (idx < NATOMS) ? g_counts[idx] : 0;
        loc[j] = s; s += v;
    }
    part[tid] = s;
    __syncthreads();
    for (int off = 1; off < 1024; off <<= 1) {
        int v = (tid >= off) ? part[tid - off] : 0;
        __syncthreads();
        part[tid] += v;
        __syncthreads();
    }
    int pre = (tid > 0) ? part[tid - 1] : 0;
#pragma unroll
    for (int j = 0; j < 10; j++) {
        int idx = base + j;
        if (idx < NATOMS) g_offs[idx] = pre + loc[j];
    }
    if (tid == 1023) g_offs[NATOMS] = part[1023];
}

// ---------------- fill CSR edge order ----------------
__global__ void k_fill(const int* __restrict__ idx_j) {
    int p = blockIdx.x * blockDim.x + threadIdx.x;
    if (p >= NPAIRS) return;
    int j = idx_j[p];
    int pos = atomicAdd(&g_cursor[j], 1);
    g_order[g_offs[j] + pos] = p;
}

// ---------------- per-atom gather reductions: q_ij, norm; also copy q into h2 ----
__global__ void k_segreduce(const float* __restrict__ q, const float* __restrict__ r_ij,
                            const float* __restrict__ d_ij) {
    int n    = blockIdx.x * 8 + (threadIdx.x >> 5);
    int lane = threadIdx.x & 31;
    if (n >= NATOMS) return;
    int beg = g_offs[n], end = g_offs[n + 1];
    int cnt = end - beg;
    float inv = 1.f / (float)max(cnt, 1);
    g_h2[(size_t)n * 384 + lane]      = q[(size_t)n * 64 + lane];
    g_h2[(size_t)n * 384 + 32 + lane] = q[(size_t)n * 64 + 32 + lane];
    for (int cr = 0; cr < 8; cr++) {
        int c = cr * 32 + lane;
        int f = c >> 2, hh = c & 3;
        float invd = 1.f / g_denom[n * 4 + hh];   // unused when cnt==0
        float ax = 0.f, ay = 0.f, az = 0.f, aq = 0.f;
        for (int tt = beg; tt < end; tt++) {
            int p = g_order[tt];
            float co   = __ldg(&g_coeffs[(size_t)p * 256 + c]);
            float rinv = 1.f / (__ldg(&d_ij[p]) + 1e-5f);
            ax += co * __ldg(&r_ij[p * 3 + 0]) * rinv;
            ay += co * __ldg(&r_ij[p * 3 + 1]) * rinv;
            az += co * __ldg(&r_ij[p * 3 + 2]) * rinv;
            aq += __ldg(&g_m[(size_t)p * 64 + f]) * __ldg(&g_e[p * 4 + hh]) * invd;
        }
        float mx = ax * inv, my = ay * inv, mz = az * inv;
        g_norm[(size_t)n * 256 + c]     = mx * mx + my * my + mz * mz;
        g_h2[(size_t)n * 384 + 64 + c]  = aq;
    }
}

// ---------------- launch ----------------
extern "C" void kernel_launch(void* const* d_in, const int* in_sizes, int n_in,
                              void* d_out, int out_size) {
    (void)in_sizes; (void)n_in; (void)out_size;
    const float* q       = (const float*)d_in[0];
    const float* r_ij    = (const float*)d_in[2];
    const float* d_ij    = (const float*)d_in[3];
    const int*   idx_i   = (const int*)d_in[4];
    const int*   idx_j   = (const int*)d_in[5];
    const float* rbf_off = (const float*)d_in[6];
    const float* rbf_w   = (const float*)d_in[7];
    const float* w_in    = (const float*)d_in[8];
    const float* b_in    = (const float*)d_in[9];
    const float* w_out1  = (const float*)d_in[10];
    const float* b_out1  = (const float*)d_in[11];
    const float* w_out2  = (const float*)d_in[12];
    const float* b_out2  = (const float*)d_in[13];
    const float* w_att   = (const float*)d_in[14];
    const float* b_att   = (const float*)d_in[15];
    const float* w_mix   = (const float*)d_in[16];
    const float* w_post1 = (const float*)d_in[17];
    const float* b_post1 = (const float*)d_in[18];
    const float* w_post2 = (const float*)d_in[19];
    const float* b_post2 = (const float*)d_in[20];
    const float* w_node1 = (const float*)d_in[21];
    const float* b_node1 = (const float*)d_in[22];
    const float* w_node2 = (const float*)d_in[23];
    const float* b_node2 = (const float*)d_in[24];
    float* out = (float*)d_out;

    k_init<<<157, 256>>>();
    k_gather<<<NPAIRS / 8, 256>>>(q, idx_i, idx_j, d_ij);
    k_gemm2<0><<<NPAIRS / 256, 256>>>(w_in, b_in, d_ij, rbf_off, rbf_w, nullptr);
    k_gemm2<1><<<NPAIRS / 256, 256>>>(w_out1, b_out1, nullptr, nullptr, nullptr, nullptr);
    k_gemm2<2><<<NPAIRS / 256, 256>>>(w_out2, b_out2, nullptr, nullptr, nullptr, nullptr);
    k_att<<<NPAIRS / 8, 256>>>(w_att, b_att, idx_j);
    k_exp<<<(NPAIRS + 255) / 256, 256>>>(idx_j);
    k_scan<<<1, 1024>>>();
    k_fill<<<(NPAIRS + 255) / 256, 256>>>(idx_j);
    k_gemm2<3><<<dim3(NPAIRS / 256, 4), 256>>>(w_mix, nullptr, nullptr, nullptr, nullptr, idx_j);
    k_segreduce<<<NATOMS / 8, 256>>>(q, r_ij, d_ij);
    k_gemm<4><<<157, 256>>>(w_post1, b_post1, nullptr, nullptr);
    k_gemm<5><<<157, 256>>>(w_post2, b_post2, nullptr, nullptr);
    k_gemm<6><<<157, 256>>>(w_node1, b_node1, nullptr, nullptr);
    k_gemm<7><<<157, 256>>>(w_node2, b_node2, q, out);
}